// round 11
// baseline (speedup 1.0000x reference)
#include <cuda_runtime.h>
#include <math.h>

#define NN   268
#define NSP  71824
#define PI_D 3.141592653589793238462643383279502884

typedef unsigned long long ull;

static __device__ __align__(16) float g_H0[512 * NSP];
static __device__ __align__(16) float g_H1[512 * NSP];
static __device__ __align__(16) float g_F [512 * NN * 40];      // [bc][x][n] n<20 Re, n>=20 Im
static __device__ __align__(16) float g_Hf[8 * 40 * 64 * 40];   // [b][m][i][n]
static __device__ __align__(16) float g_OF[8 * 40 * 64 * 40];   // [b][m][o][n]
static __device__ __align__(16) float g_G [8 * NN * 64 * 40];   // [b][x][o][n]
static __device__ __align__(16) float g_Q [8 * 256 * 256];
static __device__ __align__(16) float g_Bt  [NN * 40];          // [t][n]
static __device__ __align__(16) float g_Exc [40 * NN];
static __device__ __align__(16) float g_Exs [40 * NN];
static __device__ __align__(16) float g_Ixc [40 * NN];
static __device__ __align__(16) float g_Ixs [40 * NN];
static __device__ __align__(16) float g_Itc [20 * NN];
static __device__ __align__(16) float g_Its [20 * NN];
static __device__ __align__(16) float g_cwT[4 * 64 * 64];       // [l][i][o]
static __device__ float g_v[72];

__device__ __forceinline__ ull pk2(float lo, float hi) {
    ull r; asm("mov.b64 %0, {%1,%2};" : "=l"(r) : "f"(lo), "f"(hi)); return r;
}
__device__ __forceinline__ void fma2(ull& d, ull a, ull b) {
    asm("fma.rn.f32x2 %0, %1, %2, %3;" : "=l"(d) : "l"(a), "l"(b), "l"(d));
}
__device__ __forceinline__ float2 up2(ull v) {
    float2 r; asm("mov.b64 {%0,%1}, %2;" : "=f"(r.x), "=f"(r.y) : "l"(v)); return r;
}

// merged setup: basis tables + cw transpose + collapsed fc head vector
__global__ void k_setup(const float* __restrict__ cw,
                        const float* __restrict__ f1w, const float* __restrict__ f1b,
                        const float* __restrict__ f2w, const float* __restrict__ f2b,
                        const float* __restrict__ f3w, const float* __restrict__ f3b) {
    int blk = blockIdx.x, tid = threadIdx.x;
    const double w = 2.0 * PI_D / 268.0;
    if (blk < 147) {
        int idx = blk * 256 + tid;
        if (idx < 10720) {                       // Bt[t][n]
            int t = idx / 40, n = idx % 40;
            int k = (n < 20) ? n : n - 20;
            double a = w * ((k * t) % 268);
            g_Bt[idx] = (n < 20) ? (float)cos(a) : (float)(-sin(a));
        } else if (idx < 21440) {                // Exc/Exs[m][x]
            int q = idx - 10720;
            int m = q / NN, x = q % NN;
            int kx = (m < 20) ? m : 228 + m;
            double a = w * ((kx * x) % 268);
            g_Exc[q] = (float)cos(a);
            g_Exs[q] = (float)(-sin(a));
        } else if (idx < 32160) {                // Ixc/Ixs[m][x], incl 1/N^2
            int q = idx - 21440;
            int m = q / NN, x = q % NN;
            int kx = (m < 20) ? m : 228 + m;
            double a = w * ((kx * x) % 268);
            double sc = 1.0 / (268.0 * 268.0);
            g_Ixc[q] = (float)(cos(a) * sc);
            g_Ixs[q] = (float)(sin(a) * sc);
        } else if (idx < 37520) {                // Itc/Its[k][t]
            int q = idx - 32160;
            int k = q / NN, t = q % NN;
            double a = w * ((k * t) % 268);
            double f = (k == 0) ? 1.0 : 2.0;
            g_Itc[q] = (float)(f * cos(a));
            g_Its[q] = (float)(f * sin(a));
        }
    } else if (blk < 211) {                      // cw transpose
        int idx = (blk - 147) * 256 + tid;
        if (idx < 16384) {
            int l = idx >> 12, r = idx & 4095, i = r >> 6, o = r & 63;
            g_cwT[idx] = cw[(l << 12) + (o << 6) + i];
        }
    } else {                                     // collapsed fc head
        if (tid < 64) {
            float acc = 0.f;
            for (int j = 0; j < 32; j++) {
                float s = 0.f;
                for (int r = 0; r < 128; r++) s += f2w[j * 128 + r] * f1w[r * 64 + tid];
                acc += f3w[j] * s;
            }
            g_v[tid] = acc;
        } else if (tid == 64) {
            float acc = f3b[0];
            for (int j = 0; j < 32; j++) {
                float s = f2b[j];
                for (int r = 0; r < 128; r++) s += f2w[j * 128 + r] * f1b[r];
                acc += f3w[j] * s;
            }
            g_v[64] = acc;
        }
    }
}

// Q[b][x][t] = sum_i X[b][i][t]*wiw[x][i] + wib[x]
__global__ __launch_bounds__(256) void k_liftQ(const float* __restrict__ X,
                                               const float* __restrict__ wiw,
                                               const float* __restrict__ wib) {
    int x = blockIdx.x, b = blockIdx.y, t = threadIdx.x;
    float acc = wib[x];
#pragma unroll
    for (int i = 0; i < 8; i++)
        acc += X[((size_t)b * 8 + i) * 256 + t] * wiw[x * 8 + i];
    g_Q[((size_t)b * 256 + x) * 256 + t] = acc;
}

// H0 padded 268x268: Q*w0w[c]+w0b[c] inside, 0 outside
__global__ __launch_bounds__(256) void k_expand(const float* __restrict__ w0w,
                                                const float* __restrict__ w0b) {
    int idx = blockIdx.x * 256 + threadIdx.x;
    if (idx >= 512 * (NSP / 4)) return;
    int p4 = idx % (NSP / 4), bc = idx / (NSP / 4);
    int c = bc & 63, b = bc >> 6;
    int p = p4 * 4, x = p / NN, t0 = p % NN;
    float4 v = make_float4(0.f, 0.f, 0.f, 0.f);
    if (x < 256 && t0 < 256) {
        float4 q = *(const float4*)&g_Q[((size_t)b * 256 + x) * 256 + t0];
        float wv = w0w[c], bb = w0b[c];
        v.x = q.x * wv + bb; v.y = q.y * wv + bb;
        v.z = q.z * wv + bb; v.w = q.w * wv + bb;
    }
    *(float4*)&g_H0[(size_t)bc * NSP + p] = v;
}

// F[bc][x][n] = sum_t H[bc][x][t]*Bt[t][n]
// thread = (modegroup g=tid/64 of 8 modes, row r=tid%64). Warp-uniform Bt loads.
__global__ __launch_bounds__(320, 3) void k_dftt(int sel) {
    const float* __restrict__ H = sel ? g_H1 : g_H0;
    extern __shared__ float sH[];                  // [64][273]
    int bc = blockIdx.y, x0 = blockIdx.x * 64, tid = threadIdx.x;
    for (int idx = tid; idx < 64 * NN; idx += 320) {
        int r = idx / NN, t = idx - r * NN;
        int x = x0 + r;
        sH[r * 273 + t] = (x < NN) ? H[(size_t)bc * NSP + (size_t)x * NN + t] : 0.f;
    }
    __syncthreads();
    int g = tid / 64;                 // modegroup: modes g*8 .. g*8+7
    int r = tid - g * 64;             // row
    ull acc0 = 0, acc1 = 0, acc2 = 0, acc3 = 0;
    const float* hrow = sH + r * 273;
    const float* btbase = g_Bt + g * 8;
#pragma unroll 4
    for (int t = 0; t < NN; t++) {
        float h = hrow[t];
        ull hp = pk2(h, h);
        ulonglong2 b01 = __ldg(reinterpret_cast<const ulonglong2*>(btbase + t * 40));
        ulonglong2 b23 = __ldg(reinterpret_cast<const ulonglong2*>(btbase + t * 40 + 4));
        fma2(acc0, b01.x, hp); fma2(acc1, b01.y, hp);
        fma2(acc2, b23.x, hp); fma2(acc3, b23.y, hp);
    }
    int x = x0 + r;
    if (x < NN) {
        float2 a0 = up2(acc0), a1 = up2(acc1), a2 = up2(acc2), a3 = up2(acc3);
        float* dst = &g_F[((size_t)bc * NN + x) * 40 + g * 8];
        *(float4*)dst       = make_float4(a0.x, a0.y, a1.x, a1.y);
        *(float4*)(dst + 4) = make_float4(a2.x, a2.y, a3.x, a3.y);
    }
}

// Hf[b][m][i][n] from F via 40-mode x-DFT. Thread = (m, 4 kt), f32x2.
__global__ __launch_bounds__(200) void k_dftx() {
    __shared__ float sF[NN * 40];
    int bc = blockIdx.x, tid = threadIdx.x;
    const float* src = g_F + (size_t)bc * NN * 40;
    for (int i = tid; i < NN * 40; i += 200) sF[i] = src[i];
    __syncthreads();
    int m = tid / 5, kt0 = (tid % 5) * 4;
    ull aR0 = 0, aR1 = 0, aI0 = 0, aI1 = 0;
    const float* ec = g_Exc + m * NN;
    const float* es = g_Exs + m * NN;
#pragma unroll 2
    for (int x = 0; x < NN; x++) {
        float c = __ldg(&ec[x]), s = __ldg(&es[x]);
        ull cp = pk2(c, c), sp = pk2(s, s), sn = pk2(-s, -s);
        const ull* f = reinterpret_cast<const ull*>(&sF[x * 40 + kt0]);
        const ull* g = reinterpret_cast<const ull*>(&sF[x * 40 + 20 + kt0]);
        ull fr0 = f[0], fr1 = f[1], fi0 = g[0], fi1 = g[1];
        fma2(aR0, fr0, cp); fma2(aR0, fi0, sn);
        fma2(aR1, fr1, cp); fma2(aR1, fi1, sn);
        fma2(aI0, fr0, sp); fma2(aI0, fi0, cp);
        fma2(aI1, fr1, sp); fma2(aI1, fi1, cp);
    }
    int b = bc >> 6, i = bc & 63;
    float* dst = g_Hf + (((size_t)b * 40 + m) * 64 + i) * 40;
    float2 r0 = up2(aR0), r1 = up2(aR1), i0 = up2(aI0), i1 = up2(aI1);
    *(float4*)&dst[kt0]      = make_float4(r0.x, r0.y, r1.x, r1.y);
    *(float4*)&dst[20 + kt0] = make_float4(i0.x, i0.y, i1.x, i1.y);
}

// OF[b][m][o][kt] = sum_i Hf[b][m][i][kt] * W[l][i][o][mm][kt]  (complex)
// One block per mode; all 8 batches in smem so W is read once.
__global__ __launch_bounds__(640) void k_mix(int layer,
        const float* __restrict__ w1r, const float* __restrict__ w1i,
        const float* __restrict__ w2r, const float* __restrict__ w2i) {
    extern __shared__ float sHf[];                 // [8][2560]
    int m = blockIdx.x, tid = threadIdx.x;
    for (int idx = tid; idx < 8 * 2560; idx += 640) {
        int b = idx / 2560, rem = idx - b * 2560;
        sHf[idx] = g_Hf[((size_t)b * 40 + m) * 2560 + rem];
    }
    __syncthreads();
    int kt = tid % 20, oh = tid / 20;              // oh 0..31
    const float* wr = (m < 20) ? w1r : w2r;
    const float* wi = (m < 20) ? w1i : w2i;
    int mm = (m < 20) ? m : m - 20;
    float aR[8][2] = {}, aI[8][2] = {};
    for (int i = 0; i < 64; i++) {
        size_t o0 = ((((size_t)layer * 64 + i) * 64 + oh) * 20 + mm) * 20 + kt;
        float w0r = __ldg(&wr[o0]),          w0i = __ldg(&wi[o0]);
        float w1rv = __ldg(&wr[o0 + 12800]), w1iv = __ldg(&wi[o0 + 12800]);
        const float* hb = sHf + i * 40 + kt;
#pragma unroll
        for (int b = 0; b < 8; b++) {
            float hr = hb[b * 2560], hi = hb[b * 2560 + 20];
            aR[b][0] += hr * w0r - hi * w0i;   aI[b][0] += hr * w0i + hi * w0r;
            aR[b][1] += hr * w1rv - hi * w1iv; aI[b][1] += hr * w1iv + hi * w1rv;
        }
    }
#pragma unroll
    for (int b = 0; b < 8; b++) {
        float* d0 = g_OF + (((size_t)b * 40 + m) * 64 + oh) * 40;
        d0[kt] = aR[b][0]; d0[20 + kt] = aI[b][0];
        d0[32 * 40 + kt] = aR[b][1]; d0[32 * 40 + 20 + kt] = aI[b][1];
    }
}

// G[b][x][o][n] = inverse x-DFT of OF  (f32x2, pairs over kt)
__global__ __launch_bounds__(268) void k_invx() {
    __shared__ float sOF[1600];
    int o = blockIdx.x, b = blockIdx.y, tid = threadIdx.x;
    for (int idx = tid; idx < 1600; idx += 268)
        sOF[idx] = g_OF[(((size_t)b * 40 + idx / 40) * 64 + o) * 40 + idx % 40];
    __syncthreads();
    int x = tid;
    ull Gr[10] = {}, Gi[10] = {};
    for (int m = 0; m < 40; m++) {
        float c = __ldg(&g_Ixc[m * NN + x]), s = __ldg(&g_Ixs[m * NN + x]);
        ull cp = pk2(c, c), sp = pk2(s, s), sn = pk2(-s, -s);
        const ull* orp = reinterpret_cast<const ull*>(&sOF[m * 40]);
        const ull* oip = reinterpret_cast<const ull*>(&sOF[m * 40 + 20]);
#pragma unroll
        for (int q = 0; q < 10; q++) {
            ull o2 = orp[q], i2 = oip[q];
            fma2(Gr[q], o2, cp); fma2(Gr[q], i2, sn);
            fma2(Gi[q], o2, sp); fma2(Gi[q], i2, cp);
        }
    }
    float* dst = g_G + (((size_t)b * NN + x) * 64 + o) * 40;
#pragma unroll
    for (int q = 0; q < 10; q++) {
        float2 r = up2(Gr[q]), ii = up2(Gi[q]);
        dst[2 * q] = r.x; dst[2 * q + 1] = r.y;
        dst[20 + 2 * q] = ii.x; dst[20 + 2 * q + 1] = ii.y;
    }
}

// inv t-DFT + 1x1 conv + bias + exact GELU. Block = (x, t-half, b). 8o x 2t, 544 thr.
__global__ __launch_bounds__(544) void k_convinv(int sel, int layer,
                                                 const float* __restrict__ cb) {
    extern __shared__ float sm[];
    float* sH   = sm;                 // [64][136]
    float* sCWT = sH + 64 * 136;      // [64i][64o]
    float* sGT  = sCWT + 4096;        // [40n][68]
    float* sItc = sGT + 40 * 68;      // [20][136]
    float* sIts = sItc + 20 * 136;    // [20][136]
    const float* __restrict__ H  = sel ? g_H1 : g_H0;
    float* __restrict__       Hn = sel ? g_H0 : g_H1;
    int x = blockIdx.x, half = blockIdx.y, b = blockIdx.z;
    int tbase = half * 136;
    int tid = threadIdx.x;
    for (int idx = tid; idx < 64 * 136; idx += 544) {
        int i = idx / 136, tl = idx % 136;
        int t = tbase + tl;
        sH[idx] = (t < NN) ? H[(((size_t)b * 64 + i) * NN + x) * NN + t] : 0.f;
    }
    for (int idx = tid; idx < 4096; idx += 544)
        sCWT[idx] = g_cwT[layer * 4096 + idx];
    for (int idx = tid; idx < 2560; idx += 544) {
        int o = idx / 40, n = idx % 40;
        sGT[n * 68 + o] = g_G[((size_t)b * NN + x) * 2560 + idx];
    }
    for (int idx = tid; idx < 20 * 136; idx += 544) {
        int kt = idx / 136, tl = idx % 136;
        int t = tbase + tl;
        sItc[idx] = (t < NN) ? g_Itc[kt * NN + t] : 0.f;
        sIts[idx] = (t < NN) ? g_Its[kt * NN + t] : 0.f;
    }
    __syncthreads();
    int og = tid / 68, tq = tid % 68;
    int o0 = og * 8, t0 = tq * 2;
    ull acc[4][2] = {};                        // [o-pair][t]
#pragma unroll 2
    for (int i = 0; i < 64; i++) {
        float2 h2 = *(const float2*)&sH[i * 136 + t0];
        const ull* wp = reinterpret_cast<const ull*>(&sCWT[i * 64 + o0]);
        ull w0 = wp[0], w1 = wp[1], w2 = wp[2], w3 = wp[3];
        ull hp0 = pk2(h2.x, h2.x), hp1 = pk2(h2.y, h2.y);
        fma2(acc[0][0], w0, hp0); fma2(acc[0][1], w0, hp1);
        fma2(acc[1][0], w1, hp0); fma2(acc[1][1], w1, hp1);
        fma2(acc[2][0], w2, hp0); fma2(acc[2][1], w2, hp1);
        fma2(acc[3][0], w3, hp0); fma2(acc[3][1], w3, hp1);
    }
#pragma unroll
    for (int kt = 0; kt < 20; kt++) {
        float2 c2 = *(const float2*)&sItc[kt * 136 + t0];
        float2 s2 = *(const float2*)&sIts[kt * 136 + t0];
        const ull* gp = reinterpret_cast<const ull*>(&sGT[kt * 68 + o0]);
        const ull* ip = reinterpret_cast<const ull*>(&sGT[(20 + kt) * 68 + o0]);
        ull cc0 = pk2(c2.x, c2.x), cc1 = pk2(c2.y, c2.y);
        ull sn0 = pk2(-s2.x, -s2.x), sn1 = pk2(-s2.y, -s2.y);
#pragma unroll
        for (int p = 0; p < 4; p++) {
            ull gr = gp[p], gi = ip[p];
            fma2(acc[p][0], gr, cc0); fma2(acc[p][0], gi, sn0);
            fma2(acc[p][1], gr, cc1); fma2(acc[p][1], gi, sn1);
        }
    }
    int t0g = tbase + t0;
    if (t0g + 1 < NN) {
#pragma unroll
        for (int p = 0; p < 4; p++) {
            float2 v0 = up2(acc[p][0]), v1 = up2(acc[p][1]);
            float ol[2][2] = {{v0.x, v1.x}, {v0.y, v1.y}};
#pragma unroll
            for (int h = 0; h < 2; h++) {
                int o = o0 + 2 * p + h;
                float cbv = __ldg(&cb[layer * 64 + o]);
                float2 out;
                float v;
                v = ol[h][0] + cbv; out.x = 0.5f * v * (1.f + erff(v * 0.7071067811865475f));
                v = ol[h][1] + cbv; out.y = 0.5f * v * (1.f + erff(v * 0.7071067811865475f));
                *(float2*)&Hn[(((size_t)b * 64 + o) * NN + x) * NN + t0g] = out;
            }
        }
    }
}

__global__ __launch_bounds__(256) void k_head(int sel, float* __restrict__ out) {
    const float* __restrict__ H = sel ? g_H1 : g_H0;
    __shared__ float sv[72];
    int tid = threadIdx.x;
    if (tid < 65) sv[tid] = g_v[tid];
    __syncthreads();
    int x = blockIdx.x, b = blockIdx.y;
    const float* base = H + ((size_t)b * 64 * NN + x) * NN + tid;
    float acc = sv[64];
#pragma unroll 8
    for (int c = 0; c < 64; c++) acc += base[(size_t)c * NSP] * sv[c];
    out[((size_t)b * 256 + x) * 256 + tid] = acc;
}

extern "C" void kernel_launch(void* const* d_in, const int* in_sizes, int n_in,
                              void* d_out, int out_size) {
    (void)in_sizes; (void)n_in; (void)out_size;
    const float* x    = (const float*)d_in[0];
    const float* wi_w = (const float*)d_in[1];
    const float* wi_b = (const float*)d_in[2];
    const float* w0_w = (const float*)d_in[3];
    const float* w0_b = (const float*)d_in[4];
    const float* sw1r = (const float*)d_in[5];
    const float* sw1i = (const float*)d_in[6];
    const float* sw2r = (const float*)d_in[7];
    const float* sw2i = (const float*)d_in[8];
    const float* cw   = (const float*)d_in[9];
    const float* cb   = (const float*)d_in[10];

    const int SM_CONV = (64 * 136 + 4096 + 40 * 68 + 2 * 20 * 136) * 4;  // 83840
    const int SM_DFTT = 64 * 273 * 4;                                    // 69888
    const int SM_MIX  = 8 * 2560 * 4;                                    // 81920
    cudaFuncSetAttribute(k_convinv, cudaFuncAttributeMaxDynamicSharedMemorySize, SM_CONV);
    cudaFuncSetAttribute(k_dftt,    cudaFuncAttributeMaxDynamicSharedMemorySize, SM_DFTT);
    cudaFuncSetAttribute(k_mix,     cudaFuncAttributeMaxDynamicSharedMemorySize, SM_MIX);

    k_setup<<<212, 256>>>(cw, (const float*)d_in[11], (const float*)d_in[12],
                          (const float*)d_in[13], (const float*)d_in[14],
                          (const float*)d_in[15], (const float*)d_in[16]);
    k_liftQ<<<dim3(256, 8), 256>>>(x, wi_w, wi_b);
    k_expand<<<(512 * (NSP / 4) + 255) / 256, 256>>>(w0_w, w0_b);

    int sel = 0;
    for (int l = 0; l < 4; l++) {
        k_dftt<<<dim3(5, 512), 320, SM_DFTT>>>(sel);
        k_dftx<<<512, 200>>>();
        k_mix<<<40, 640, SM_MIX>>>(l, sw1r, sw1i, sw2r, sw2i);
        k_invx<<<dim3(64, 8), 268>>>();
        k_convinv<<<dim3(NN, 2, 8), 544, SM_CONV>>>(sel, l, cb);
        sel ^= 1;
    }
    k_head<<<dim3(256, 8), 256>>>(sel, (float*)d_out);
}

// round 12
// speedup vs baseline: 1.1535x; 1.1535x over previous
#include <cuda_runtime.h>
#include <math.h>

#define NN   268
#define NSP  71824
#define PI_D 3.141592653589793238462643383279502884

typedef unsigned long long ull;

static __device__ __align__(16) float g_H0[512 * NSP];
static __device__ __align__(16) float g_H1[512 * NSP];
static __device__ __align__(16) float g_F [512 * NN * 40];      // [bc][x][n] n<20 Re, n>=20 Im
static __device__ __align__(16) float g_Hf[8 * 40 * 64 * 40];   // [b][m][i][n]
static __device__ __align__(16) float g_OF[8 * 40 * 64 * 40];   // [b][m][o][n]
static __device__ __align__(16) float g_G [8 * NN * 64 * 40];   // [b][x][o][n]
static __device__ __align__(16) float g_Q [8 * 256 * 256];
static __device__ __align__(16) float g_Bt  [NN * 40];          // [t][n]
static __device__ __align__(16) float g_Exc [40 * NN];
static __device__ __align__(16) float g_Exs [40 * NN];
static __device__ __align__(16) float g_Ixc [40 * NN];
static __device__ __align__(16) float g_Ixs [40 * NN];
static __device__ __align__(16) float g_Itc [20 * NN];
static __device__ __align__(16) float g_Its [20 * NN];
static __device__ __align__(16) float g_cwT[4 * 64 * 64];       // [l][i][o]
static __device__ float g_v[72];

__device__ __forceinline__ ull pk2(float lo, float hi) {
    ull r; asm("mov.b64 %0, {%1,%2};" : "=l"(r) : "f"(lo), "f"(hi)); return r;
}
__device__ __forceinline__ void fma2(ull& d, ull a, ull b) {
    asm("fma.rn.f32x2 %0, %1, %2, %3;" : "=l"(d) : "l"(a), "l"(b), "l"(d));
}
__device__ __forceinline__ float2 up2(ull v) {
    float2 r; asm("mov.b64 {%0,%1}, %2;" : "=f"(r.x), "=f"(r.y) : "l"(v)); return r;
}

// merged setup: basis tables + cw transpose + collapsed fc head vector
__global__ void k_setup(const float* __restrict__ cw,
                        const float* __restrict__ f1w, const float* __restrict__ f1b,
                        const float* __restrict__ f2w, const float* __restrict__ f2b,
                        const float* __restrict__ f3w, const float* __restrict__ f3b) {
    int blk = blockIdx.x, tid = threadIdx.x;
    const double w = 2.0 * PI_D / 268.0;
    if (blk < 147) {
        int idx = blk * 256 + tid;
        if (idx < 10720) {                       // Bt[t][n]
            int t = idx / 40, n = idx % 40;
            int k = (n < 20) ? n : n - 20;
            double a = w * ((k * t) % 268);
            g_Bt[idx] = (n < 20) ? (float)cos(a) : (float)(-sin(a));
        } else if (idx < 21440) {                // Exc/Exs[m][x]
            int q = idx - 10720;
            int m = q / NN, x = q % NN;
            int kx = (m < 20) ? m : 228 + m;
            double a = w * ((kx * x) % 268);
            g_Exc[q] = (float)cos(a);
            g_Exs[q] = (float)(-sin(a));
        } else if (idx < 32160) {                // Ixc/Ixs[m][x], incl 1/N^2
            int q = idx - 21440;
            int m = q / NN, x = q % NN;
            int kx = (m < 20) ? m : 228 + m;
            double a = w * ((kx * x) % 268);
            double sc = 1.0 / (268.0 * 268.0);
            g_Ixc[q] = (float)(cos(a) * sc);
            g_Ixs[q] = (float)(sin(a) * sc);
        } else if (idx < 37520) {                // Itc/Its[k][t]
            int q = idx - 32160;
            int k = q / NN, t = q % NN;
            double a = w * ((k * t) % 268);
            double f = (k == 0) ? 1.0 : 2.0;
            g_Itc[q] = (float)(f * cos(a));
            g_Its[q] = (float)(f * sin(a));
        }
    } else if (blk < 211) {                      // cw transpose
        int idx = (blk - 147) * 256 + tid;
        if (idx < 16384) {
            int l = idx >> 12, r = idx & 4095, i = r >> 6, o = r & 63;
            g_cwT[idx] = cw[(l << 12) + (o << 6) + i];
        }
    } else {                                     // collapsed fc head
        if (tid < 64) {
            float acc = 0.f;
            for (int j = 0; j < 32; j++) {
                float s = 0.f;
                for (int r = 0; r < 128; r++) s += f2w[j * 128 + r] * f1w[r * 64 + tid];
                acc += f3w[j] * s;
            }
            g_v[tid] = acc;
        } else if (tid == 64) {
            float acc = f3b[0];
            for (int j = 0; j < 32; j++) {
                float s = f2b[j];
                for (int r = 0; r < 128; r++) s += f2w[j * 128 + r] * f1b[r];
                acc += f3w[j] * s;
            }
            g_v[64] = acc;
        }
    }
}

// Q[b][x][t] = sum_i X[b][i][t]*wiw[x][i] + wib[x]
__global__ __launch_bounds__(256) void k_liftQ(const float* __restrict__ X,
                                               const float* __restrict__ wiw,
                                               const float* __restrict__ wib) {
    int x = blockIdx.x, b = blockIdx.y, t = threadIdx.x;
    float acc = wib[x];
#pragma unroll
    for (int i = 0; i < 8; i++)
        acc += X[((size_t)b * 8 + i) * 256 + t] * wiw[x * 8 + i];
    g_Q[((size_t)b * 256 + x) * 256 + t] = acc;
}

// H0 padded 268x268: Q*w0w[c]+w0b[c] inside, 0 outside
__global__ __launch_bounds__(256) void k_expand(const float* __restrict__ w0w,
                                                const float* __restrict__ w0b) {
    int idx = blockIdx.x * 256 + threadIdx.x;
    if (idx >= 512 * (NSP / 4)) return;
    int p4 = idx % (NSP / 4), bc = idx / (NSP / 4);
    int c = bc & 63, b = bc >> 6;
    int p = p4 * 4, x = p / NN, t0 = p % NN;
    float4 v = make_float4(0.f, 0.f, 0.f, 0.f);
    if (x < 256 && t0 < 256) {
        float4 q = *(const float4*)&g_Q[((size_t)b * 256 + x) * 256 + t0];
        float wv = w0w[c], bb = w0b[c];
        v.x = q.x * wv + bb; v.y = q.y * wv + bb;
        v.z = q.z * wv + bb; v.w = q.w * wv + bb;
    }
    *(float4*)&g_H0[(size_t)bc * NSP + p] = v;
}

// F[bc][x][n] = sum_t H[bc][x][t]*Bt[t][n]
// Bt staged in smem (kills the LDG dispatch floor). thread = (modegroup, row).
__global__ __launch_bounds__(320) void k_dftt(int sel) {
    const float* __restrict__ H = sel ? g_H1 : g_H0;
    extern __shared__ float sm[];
    float* sBt = sm;                  // [268][40]
    float* sH  = sm + 10720;          // [64][269]
    int bc = blockIdx.y, x0 = blockIdx.x * 64, tid = threadIdx.x;
    for (int idx = tid; idx < 10720; idx += 320) sBt[idx] = g_Bt[idx];
    for (int idx = tid; idx < 64 * NN; idx += 320) {
        int r = idx / NN, t = idx - r * NN;
        int x = x0 + r;
        sH[r * 269 + t] = (x < NN) ? H[(size_t)bc * NSP + (size_t)x * NN + t] : 0.f;
    }
    __syncthreads();
    int g = tid / 64;                 // modegroup: modes g*8 .. g*8+7 (warp-uniform)
    int r = tid - g * 64;             // row
    ull acc0 = 0, acc1 = 0, acc2 = 0, acc3 = 0;
    const float* hrow = sH + r * 269;
    const float* btbase = sBt + g * 8;
#pragma unroll 4
    for (int t = 0; t < NN; t++) {
        float h = hrow[t];
        ull hp = pk2(h, h);
        const ulonglong2* b2 = reinterpret_cast<const ulonglong2*>(btbase + t * 40);
        ulonglong2 b01 = b2[0], b23 = b2[1];
        fma2(acc0, b01.x, hp); fma2(acc1, b01.y, hp);
        fma2(acc2, b23.x, hp); fma2(acc3, b23.y, hp);
    }
    int x = x0 + r;
    if (x < NN) {
        float2 a0 = up2(acc0), a1 = up2(acc1), a2 = up2(acc2), a3 = up2(acc3);
        float* dst = &g_F[((size_t)bc * NN + x) * 40 + g * 8];
        *(float4*)dst       = make_float4(a0.x, a0.y, a1.x, a1.y);
        *(float4*)(dst + 4) = make_float4(a2.x, a2.y, a3.x, a3.y);
    }
}

// Hf[b][m][i][n] from F via 40-mode x-DFT. Thread = (m, 4 kt), f32x2.
__global__ __launch_bounds__(200) void k_dftx() {
    __shared__ float sF[NN * 40];
    int bc = blockIdx.x, tid = threadIdx.x;
    const float* src = g_F + (size_t)bc * NN * 40;
    for (int i = tid; i < NN * 40; i += 200) sF[i] = src[i];
    __syncthreads();
    int m = tid / 5, kt0 = (tid % 5) * 4;
    ull aR0 = 0, aR1 = 0, aI0 = 0, aI1 = 0;
    const float* ec = g_Exc + m * NN;
    const float* es = g_Exs + m * NN;
#pragma unroll 2
    for (int x = 0; x < NN; x++) {
        float c = __ldg(&ec[x]), s = __ldg(&es[x]);
        ull cp = pk2(c, c), sp = pk2(s, s), sn = pk2(-s, -s);
        const ull* f = reinterpret_cast<const ull*>(&sF[x * 40 + kt0]);
        const ull* g = reinterpret_cast<const ull*>(&sF[x * 40 + 20 + kt0]);
        ull fr0 = f[0], fr1 = f[1], fi0 = g[0], fi1 = g[1];
        fma2(aR0, fr0, cp); fma2(aR0, fi0, sn);
        fma2(aR1, fr1, cp); fma2(aR1, fi1, sn);
        fma2(aI0, fr0, sp); fma2(aI0, fi0, cp);
        fma2(aI1, fr1, sp); fma2(aI1, fi1, cp);
    }
    int b = bc >> 6, i = bc & 63;
    float* dst = g_Hf + (((size_t)b * 40 + m) * 64 + i) * 40;
    float2 r0 = up2(aR0), r1 = up2(aR1), i0 = up2(aI0), i1 = up2(aI1);
    *(float4*)&dst[kt0]      = make_float4(r0.x, r0.y, r1.x, r1.y);
    *(float4*)&dst[20 + kt0] = make_float4(i0.x, i0.y, i1.x, i1.y);
}

// OF[b][m][o][kt] = sum_i Hf[b][m][i][kt] * W[l][i][o][mm][kt]  (complex)
__global__ __launch_bounds__(640) void k_mix(int layer,
        const float* __restrict__ w1r, const float* __restrict__ w1i,
        const float* __restrict__ w2r, const float* __restrict__ w2i) {
    __shared__ float sH[2560];
    int m = blockIdx.x, b = blockIdx.y, tid = threadIdx.x;
    const float* src = g_Hf + ((size_t)b * 40 + m) * 2560;
    for (int i = tid; i < 2560; i += 640) sH[i] = src[i];
    __syncthreads();
    int kt = tid % 20, oh = tid / 20;
    const float* wr = (m < 20) ? w1r : w2r;
    const float* wi = (m < 20) ? w1i : w2i;
    int mm = (m < 20) ? m : m - 20;
    float aR0 = 0.f, aI0 = 0.f, aR1 = 0.f, aI1 = 0.f;
    for (int i = 0; i < 64; i++) {
        float hr = sH[i * 40 + kt], hi = sH[i * 40 + 20 + kt];
        size_t o0 = ((((size_t)layer * 64 + i) * 64 + oh) * 20 + mm) * 20 + kt;
        float w0r = __ldg(&wr[o0]),          w0i = __ldg(&wi[o0]);
        float w1rv = __ldg(&wr[o0 + 12800]), w1iv = __ldg(&wi[o0 + 12800]);
        aR0 += hr * w0r - hi * w0i;   aI0 += hr * w0i + hi * w0r;
        aR1 += hr * w1rv - hi * w1iv; aI1 += hr * w1iv + hi * w1rv;
    }
    float* d0 = g_OF + (((size_t)b * 40 + m) * 64 + oh) * 40;
    d0[kt] = aR0; d0[20 + kt] = aI0;
    d0[32 * 40 + kt] = aR1; d0[32 * 40 + 20 + kt] = aI1;
}

// G[b][x][o][n] = inverse x-DFT of OF  (f32x2, pairs over kt)
__global__ __launch_bounds__(268) void k_invx() {
    __shared__ float sOF[1600];
    int o = blockIdx.x, b = blockIdx.y, tid = threadIdx.x;
    for (int idx = tid; idx < 1600; idx += 268)
        sOF[idx] = g_OF[(((size_t)b * 40 + idx / 40) * 64 + o) * 40 + idx % 40];
    __syncthreads();
    int x = tid;
    ull Gr[10] = {}, Gi[10] = {};
    for (int m = 0; m < 40; m++) {
        float c = __ldg(&g_Ixc[m * NN + x]), s = __ldg(&g_Ixs[m * NN + x]);
        ull cp = pk2(c, c), sp = pk2(s, s), sn = pk2(-s, -s);
        const ull* orp = reinterpret_cast<const ull*>(&sOF[m * 40]);
        const ull* oip = reinterpret_cast<const ull*>(&sOF[m * 40 + 20]);
#pragma unroll
        for (int q = 0; q < 10; q++) {
            ull o2 = orp[q], i2 = oip[q];
            fma2(Gr[q], o2, cp); fma2(Gr[q], i2, sn);
            fma2(Gi[q], o2, sp); fma2(Gi[q], i2, cp);
        }
    }
    float* dst = g_G + (((size_t)b * NN + x) * 64 + o) * 40;
#pragma unroll
    for (int q = 0; q < 10; q++) {
        float2 r = up2(Gr[q]), ii = up2(Gi[q]);
        dst[2 * q] = r.x; dst[2 * q + 1] = r.y;
        dst[20 + 2 * q] = ii.x; dst[20 + 2 * q + 1] = ii.y;
    }
}

// inv t-DFT + 1x1 conv + bias + exact GELU. Block = (x, t-half, b). 8o x 2t, 544 thr.
__global__ __launch_bounds__(544) void k_convinv(int sel, int layer,
                                                 const float* __restrict__ cb) {
    extern __shared__ float sm[];
    float* sH   = sm;                 // [64][136]
    float* sCWT = sH + 64 * 136;      // [64i][64o]
    float* sGT  = sCWT + 4096;        // [40n][68]
    float* sItc = sGT + 40 * 68;      // [20][136]
    float* sIts = sItc + 20 * 136;    // [20][136]
    const float* __restrict__ H  = sel ? g_H1 : g_H0;
    float* __restrict__       Hn = sel ? g_H0 : g_H1;
    int x = blockIdx.x, half = blockIdx.y, b = blockIdx.z;
    int tbase = half * 136;
    int tid = threadIdx.x;
    for (int idx = tid; idx < 64 * 136; idx += 544) {
        int i = idx / 136, tl = idx % 136;
        int t = tbase + tl;
        sH[idx] = (t < NN) ? H[(((size_t)b * 64 + i) * NN + x) * NN + t] : 0.f;
    }
    for (int idx = tid; idx < 4096; idx += 544)
        sCWT[idx] = g_cwT[layer * 4096 + idx];
    for (int idx = tid; idx < 2560; idx += 544) {
        int o = idx / 40, n = idx % 40;
        sGT[n * 68 + o] = g_G[((size_t)b * NN + x) * 2560 + idx];
    }
    for (int idx = tid; idx < 20 * 136; idx += 544) {
        int kt = idx / 136, tl = idx % 136;
        int t = tbase + tl;
        sItc[idx] = (t < NN) ? g_Itc[kt * NN + t] : 0.f;
        sIts[idx] = (t < NN) ? g_Its[kt * NN + t] : 0.f;
    }
    __syncthreads();
    int og = tid / 68, tq = tid % 68;
    int o0 = og * 8, t0 = tq * 2;
    ull acc[4][2] = {};                        // [o-pair][t]
#pragma unroll 2
    for (int i = 0; i < 64; i++) {
        float2 h2 = *(const float2*)&sH[i * 136 + t0];
        const ull* wp = reinterpret_cast<const ull*>(&sCWT[i * 64 + o0]);
        ull w0 = wp[0], w1 = wp[1], w2 = wp[2], w3 = wp[3];
        ull hp0 = pk2(h2.x, h2.x), hp1 = pk2(h2.y, h2.y);
        fma2(acc[0][0], w0, hp0); fma2(acc[0][1], w0, hp1);
        fma2(acc[1][0], w1, hp0); fma2(acc[1][1], w1, hp1);
        fma2(acc[2][0], w2, hp0); fma2(acc[2][1], w2, hp1);
        fma2(acc[3][0], w3, hp0); fma2(acc[3][1], w3, hp1);
    }
#pragma unroll
    for (int kt = 0; kt < 20; kt++) {
        float2 c2 = *(const float2*)&sItc[kt * 136 + t0];
        float2 s2 = *(const float2*)&sIts[kt * 136 + t0];
        const ull* gp = reinterpret_cast<const ull*>(&sGT[kt * 68 + o0]);
        const ull* ip = reinterpret_cast<const ull*>(&sGT[(20 + kt) * 68 + o0]);
        ull cc0 = pk2(c2.x, c2.x), cc1 = pk2(c2.y, c2.y);
        ull sn0 = pk2(-s2.x, -s2.x), sn1 = pk2(-s2.y, -s2.y);
#pragma unroll
        for (int p = 0; p < 4; p++) {
            ull gr = gp[p], gi = ip[p];
            fma2(acc[p][0], gr, cc0); fma2(acc[p][0], gi, sn0);
            fma2(acc[p][1], gr, cc1); fma2(acc[p][1], gi, sn1);
        }
    }
    int t0g = tbase + t0;
    if (t0g + 1 < NN) {
#pragma unroll
        for (int p = 0; p < 4; p++) {
            float2 v0 = up2(acc[p][0]), v1 = up2(acc[p][1]);
            float ol[2][2] = {{v0.x, v1.x}, {v0.y, v1.y}};
#pragma unroll
            for (int h = 0; h < 2; h++) {
                int o = o0 + 2 * p + h;
                float cbv = __ldg(&cb[layer * 64 + o]);
                float2 out;
                float v;
                v = ol[h][0] + cbv; out.x = 0.5f * v * (1.f + erff(v * 0.7071067811865475f));
                v = ol[h][1] + cbv; out.y = 0.5f * v * (1.f + erff(v * 0.7071067811865475f));
                *(float2*)&Hn[(((size_t)b * 64 + o) * NN + x) * NN + t0g] = out;
            }
        }
    }
}

__global__ __launch_bounds__(256) void k_head(int sel, float* __restrict__ out) {
    const float* __restrict__ H = sel ? g_H1 : g_H0;
    __shared__ float sv[72];
    int tid = threadIdx.x;
    if (tid < 65) sv[tid] = g_v[tid];
    __syncthreads();
    int x = blockIdx.x, b = blockIdx.y;
    const float* base = H + ((size_t)b * 64 * NN + x) * NN + tid;
    float acc = sv[64];
#pragma unroll 8
    for (int c = 0; c < 64; c++) acc += base[(size_t)c * NSP] * sv[c];
    out[((size_t)b * 256 + x) * 256 + tid] = acc;
}

extern "C" void kernel_launch(void* const* d_in, const int* in_sizes, int n_in,
                              void* d_out, int out_size) {
    (void)in_sizes; (void)n_in; (void)out_size;
    const float* x    = (const float*)d_in[0];
    const float* wi_w = (const float*)d_in[1];
    const float* wi_b = (const float*)d_in[2];
    const float* w0_w = (const float*)d_in[3];
    const float* w0_b = (const float*)d_in[4];
    const float* sw1r = (const float*)d_in[5];
    const float* sw1i = (const float*)d_in[6];
    const float* sw2r = (const float*)d_in[7];
    const float* sw2i = (const float*)d_in[8];
    const float* cw   = (const float*)d_in[9];
    const float* cb   = (const float*)d_in[10];

    const int SM_CONV = (64 * 136 + 4096 + 40 * 68 + 2 * 20 * 136) * 4;  // 83840
    const int SM_DFTT = (10720 + 64 * 269) * 4;                          // 111744
    cudaFuncSetAttribute(k_convinv, cudaFuncAttributeMaxDynamicSharedMemorySize, SM_CONV);
    cudaFuncSetAttribute(k_dftt,    cudaFuncAttributeMaxDynamicSharedMemorySize, SM_DFTT);

    k_setup<<<212, 256>>>(cw, (const float*)d_in[11], (const float*)d_in[12],
                          (const float*)d_in[13], (const float*)d_in[14],
                          (const float*)d_in[15], (const float*)d_in[16]);
    k_liftQ<<<dim3(256, 8), 256>>>(x, wi_w, wi_b);
    k_expand<<<(512 * (NSP / 4) + 255) / 256, 256>>>(w0_w, w0_b);

    int sel = 0;
    for (int l = 0; l < 4; l++) {
        k_dftt<<<dim3(5, 512), 320, SM_DFTT>>>(sel);
        k_dftx<<<512, 200>>>();
        k_mix<<<dim3(40, 8), 640>>>(l, sw1r, sw1i, sw2r, sw2i);
        k_invx<<<dim3(64, 8), 268>>>();
        k_convinv<<<dim3(NN, 2, 8), 544, SM_CONV>>>(sel, l, cb);
        sel ^= 1;
    }
    k_head<<<dim3(256, 8), 256>>>(sel, (float*)d_out);
}